// round 13
// baseline (speedup 1.0000x reference)
#include <cuda_runtime.h>
#include <cuda_bf16.h>
#include <math.h>

#define BATCH 4096
#define NNB   64
#define DM    256
#define NH    8
#define HD    32
#define SCALE 0.17677669529663687f   // 1/sqrt(32)

// ---------------- f32x2 packed helpers ----------------
__device__ __forceinline__ void fma2(unsigned long long& d,
                                     unsigned long long a,
                                     unsigned long long b) {
    asm("fma.rn.f32x2 %0, %1, %2, %0;" : "+l"(d) : "l"(a), "l"(b));
}
__device__ __forceinline__ float2 upk(unsigned long long v) {
    float2 r;
    asm("mov.b64 {%0, %1}, %2;" : "=f"(r.x), "=f"(r.y) : "l"(v));
    return r;
}
__device__ __forceinline__ unsigned int s2u(const void* p) {
    unsigned int a;
    asm("{ .reg .u64 t; cvta.to.shared.u64 t, %1; cvt.u32.u64 %0, t; }"
        : "=r"(a) : "l"(p));
    return a;
}
__device__ __forceinline__ void cp16(unsigned int saddr, const void* g) {
    asm volatile("cp.async.ca.shared.global [%0], [%1], 16;"
                 :: "r"(saddr), "l"(g) : "memory");
}

// ---------------- scratch ----------------
__device__ float d_Q  [BATCH * DM];
__device__ float d_U  [BATCH * NH * DM];
__device__ float d_ctx[BATCH * NH * DM];
__device__ float d_att[BATCH * DM];
__device__ float d_y  [BATCH * DM];
__device__ float d_WkT[NH * DM * HD];      // [h][c][d]
__device__ float d_WoT[DM * DM];
__device__ float d_Wc [DM * DM];
__device__ float d_b1 [DM];
__device__ unsigned int d_or = 0u;         // OR of odd words; 0 => int64

// ---------------- prep: transposes + b1 + edge-dtype detect ----------------
__global__ void prep_kernel(const float* __restrict__ Wk,
                            const float* __restrict__ Wo,
                            const float* __restrict__ Wf,
                            const float* __restrict__ bo,
                            const float* __restrict__ bfv,
                            const unsigned int* __restrict__ e32) {
    const int blk = blockIdx.x, t = threadIdx.x;
    const int i = blk * 256 + t;                 // 0..65535
    { int dd = i & 31, c = (i >> 5) & 255, h = i >> 13;
      d_WkT[i] = Wk[(h * HD + dd) * DM + c]; }
    { int j = i >> 8, m = i & 255;
      d_WoT[i] = Wo[m * DM + j]; }
    if (blk < 32) {
        int o = blk * 8 + (t >> 5), l = t & 31;
        float s = 0.f;
        #pragma unroll
        for (int m = l; m < DM; m += 32) s += Wf[o * 2 * DM + m] * bo[m];
        #pragma unroll
        for (int off = 16; off; off >>= 1) s += __shfl_xor_sync(0xffffffffu, s, off);
        if (l == 0) d_b1[o] = bfv[o] + s;
    }
    unsigned int acc = 0u;
    #pragma unroll
    for (int w = i; w < BATCH * NNB; w += 65536) acc |= e32[2 * w + 1];
    #pragma unroll
    for (int o = 16; o; o >>= 1) acc |= __shfl_xor_sync(0xffffffffu, acc, o);
    __shared__ unsigned int sOr;
    if (t == 0) sOr = 0u;
    __syncthreads();
    if ((t & 31) == 0 && acc) atomicOr(&sOr, acc);
    __syncthreads();
    if (t == 0 && sOr) atomicOr(&d_or, sOr);
}

// ---------------- double-buffered NT GEMM (plain FFMA, proven R9) -----------
template<int BM, int BN, int TM, int TN>
__global__ void gemm2_kernel(const float* __restrict__ A1, int lda1, long az1,
                             const float* __restrict__ B1, int ldb1, long bz1,
                             const float* __restrict__ A2, int lda2,
                             const float* __restrict__ B2, int ldb2,
                             const float* __restrict__ bias, long biasz,
                             float* __restrict__ C, int ldc, long cz,
                             int K1, int Ktot, float alpha) {
    constexpr int BK = 16;
    constexpr int NT = (BM / TM) * (BN / TN);
    constexpr int PAD = 4;
    constexpr int A4 = BM * BK / 4;
    constexpr int B4 = BN * BK / 4;
    constexpr int NA = (A4 + NT - 1) / NT;
    constexpr int NB = (B4 + NT - 1) / NT;

    __shared__ float As[2][BK][BM + PAD];
    __shared__ float Bs[2][BK][BN + PAD];

    const int tid = threadIdx.x;
    const int tx = tid % (BN / TN);
    const int ty = tid / (BN / TN);
    const int row0 = blockIdx.y * BM;
    const int col0 = blockIdx.x * BN;
    const int z = blockIdx.z;

    const float* A1g = A1 + (long)z * az1;
    const float* B1g = B1 + (long)z * bz1;
    float* Cg = C + (long)z * cz;
    const float* biasg = bias ? bias + (long)z * biasz : nullptr;

    float4 ra[NA], rb[NB];

    auto fetch = [&](int t) {
        int k0 = t * BK;
        const float *Ap, *Bp; int lda, ldb, k;
        if (k0 < K1) { Ap = A1g; lda = lda1; Bp = B1g; ldb = ldb1; k = k0; }
        else         { Ap = A2;  lda = lda2; Bp = B2;  ldb = ldb2; k = k0 - K1; }
        #pragma unroll
        for (int i = 0; i < NA; i++) {
            int f = tid + i * NT;
            if (f < A4) {
                int r = f >> 2, kq = f & 3;
                ra[i] = *reinterpret_cast<const float4*>(Ap + (long)(row0 + r) * lda + k + kq * 4);
            }
        }
        #pragma unroll
        for (int i = 0; i < NB; i++) {
            int f = tid + i * NT;
            if (f < B4) {
                int n = f >> 2, kq = f & 3;
                rb[i] = *reinterpret_cast<const float4*>(Bp + (long)(col0 + n) * ldb + k + kq * 4);
            }
        }
    };
    auto stage = [&](int buf) {
        #pragma unroll
        for (int i = 0; i < NA; i++) {
            int f = tid + i * NT;
            if (f < A4) {
                int r = f >> 2, kq = f & 3;
                As[buf][kq * 4 + 0][r] = ra[i].x;
                As[buf][kq * 4 + 1][r] = ra[i].y;
                As[buf][kq * 4 + 2][r] = ra[i].z;
                As[buf][kq * 4 + 3][r] = ra[i].w;
            }
        }
        #pragma unroll
        for (int i = 0; i < NB; i++) {
            int f = tid + i * NT;
            if (f < B4) {
                int n = f >> 2, kq = f & 3;
                Bs[buf][kq * 4 + 0][n] = rb[i].x;
                Bs[buf][kq * 4 + 1][n] = rb[i].y;
                Bs[buf][kq * 4 + 2][n] = rb[i].z;
                Bs[buf][kq * 4 + 3][n] = rb[i].w;
            }
        }
    };

    float acc[TM][TN];
    #pragma unroll
    for (int i = 0; i < TM; i++)
        #pragma unroll
        for (int j = 0; j < TN; j++) acc[i][j] = 0.f;

    fetch(0); stage(0); __syncthreads();
    const int ntiles = Ktot / BK;
    for (int t = 0; t < ntiles; t++) {
        int cur = t & 1;
        if (t + 1 < ntiles) fetch(t + 1);
        #pragma unroll
        for (int kk = 0; kk < BK; kk++) {
            float a[TM], b[TN];
            #pragma unroll
            for (int i = 0; i < TM; i++) a[i] = As[cur][kk][ty * TM + i];
            #pragma unroll
            for (int j = 0; j < TN; j++) b[j] = Bs[cur][kk][tx * TN + j];
            #pragma unroll
            for (int i = 0; i < TM; i++)
                #pragma unroll
                for (int j = 0; j < TN; j++) acc[i][j] += a[i] * b[j];
        }
        if (t + 1 < ntiles) stage(cur ^ 1);
        __syncthreads();
    }

    #pragma unroll
    for (int i = 0; i < TM; i++) {
        int r = row0 + ty * TM + i;
        #pragma unroll
        for (int j = 0; j < TN; j++) {
            int c = col0 + tx * TN + j;
            float v = alpha * acc[i][j];
            if (biasg) v += biasg[c];
            Cg[(long)r * ldc + c] = v;
        }
    }
}

// ---------------- fused attention v9 (smem diet -> 3 CTAs/SM) ---------------
// smem floats (total 18824 = 75296 B):
//   nbt   [0, 16640)       transposed float4 tile, slot c4 (0..63) x 65 (n+pad)
//   u_s   [16640, 18688)   float4-interleaved: f4 slot = h*64 + i*4 + q
//     logit aliases u_s[0..576)    (written after phase-1 barrier; [n*9+h])
//     adup  aliases u_s[1024..2048) ([n*16 + h*2 + {0,1}])
//   tbl   [18688, 18752)   [e*8 + h]
//   kb_s  [18752, 18760)
//   et_s  [18760, 18824)   ints
//   part2 (phase 2) aliases [0, 16384) floats over dead nbt
#define U_OFF     16640
#define LOGIT_OFF 16640
#define ADUP_OFF  17664
#define TBL_OFF   18688
#define KB_OFF    18752
#define ET_OFF    18760
#define ATTN_SMEM_BYTES (18824 * 4)

__global__ __launch_bounds__(256, 3) void attn_kernel(
        const float* __restrict__ nb,
        const unsigned int* __restrict__ e32,
        const float* __restrict__ ebt,
        const float* __restrict__ bk) {
    extern __shared__ __align__(16) float sm[];
    float4* nbt   = (float4*)sm;
    float*  u_s   = sm + U_OFF;
    float*  logit = sm + LOGIT_OFF;
    float*  adup  = sm + ADUP_OFF;
    float*  tbl   = sm + TBL_OFF;
    float*  kb_s  = sm + KB_OFF;
    int*    et_s  = (int*)(sm + ET_OFF);

    const int b = blockIdx.x;
    const int t = threadIdx.x;
    const int w = t >> 5, l = t & 31;

    // ---- stage nb (transposed) + u (interleaved) via cp.async ----
    const float4* nbg = (const float4*)(nb + (long)b * NNB * DM);
    #pragma unroll
    for (int i = 0; i < 16; i++) {
        int f = t + i * 256;
        int row = f >> 6, c4 = f & 63;
        cp16(s2u(&nbt[c4 * 65 + row]), &nbg[f]);
    }
    const float4* ug = (const float4*)(d_U + (long)b * 2048);
    #pragma unroll
    for (int k = 0; k < 2; k++) {
        int f = t + k * 256;                 // h*64 + c4g
        int h = f >> 6, c4g = f & 63;
        int slot = h * 64 + (c4g & 15) * 4 + (c4g >> 4);
        cp16(s2u(u_s + slot * 4), &ug[f]);
    }
    asm volatile("cp.async.commit_group;" ::: "memory");

    // ---- overlapped small loads ----
    if (t < NNB) {
        int v = (d_or == 0u) ? (int)e32[(long)b * (2 * NNB) + 2 * t]
                             : (int)e32[(long)b * NNB + t];
        et_s[t] = v;
        tbl[t] = ebt[t];                     // [e*8+h]
    }
    {
        float s = d_Q[(long)b * DM + w * HD + l] * bk[w * HD + l];
        #pragma unroll
        for (int o = 16; o; o >>= 1) s += __shfl_xor_sync(0xffffffffu, s, o);
        if (l == 0) kb_s[w] = SCALE * s;
    }
    asm volatile("cp.async.wait_group 0;" ::: "memory");
    __syncthreads();

    // ---- phase 1: warp w owns neighbors [8w,8w+8); lane = (n = l&7, q = l>>3)
    float lv[NH];
    {
        const int n = 8 * w + (l & 7);
        const int q = l >> 3;
        unsigned long long acc[NH];
        #pragma unroll
        for (int h = 0; h < NH; h++) acc[h] = 0ull;
        #pragma unroll
        for (int i = 0; i < 16; i++) {
            int slot = q * 16 + i;
            ulonglong2 x = *reinterpret_cast<const ulonglong2*>(nbt + slot * 65 + n);
            #pragma unroll
            for (int h = 0; h < NH; h++) {
                ulonglong2 u = *reinterpret_cast<const ulonglong2*>(
                    u_s + (h * 64 + i * 4 + q) * 4);
                fma2(acc[h], u.x, x.x);
                fma2(acc[h], u.y, x.y);
            }
        }
        #pragma unroll
        for (int h = 0; h < NH; h++) {
            float2 v = upk(acc[h]);
            lv[h] = v.x + v.y;
            lv[h] += __shfl_xor_sync(0xffffffffu, lv[h], 8);
            lv[h] += __shfl_xor_sync(0xffffffffu, lv[h], 16);
        }
    }
    __syncthreads();             // all u reads done -> logit may alias u_s
    if (l < 8) {
        const int n = 8 * w + l;
        #pragma unroll
        for (int h = 0; h < NH; h++) logit[n * 9 + h] = lv[h];
    }
    __syncthreads();

    // ---- softmax: warp w = head w; writes adup pairs ----
    {
        float lg0 = kb_s[w] + tbl[et_s[l] * NH + w]      + logit[l * 9 + w];
        float lg1 = kb_s[w] + tbl[et_s[l + 32] * NH + w] + logit[(l + 32) * 9 + w];
        float m = fmaxf(lg0, lg1);
        #pragma unroll
        for (int o = 16; o; o >>= 1) m = fmaxf(m, __shfl_xor_sync(0xffffffffu, m, o));
        float e0 = __expf(lg0 - m), e1 = __expf(lg1 - m);
        float s = e0 + e1;
        #pragma unroll
        for (int o = 16; o; o >>= 1) s += __shfl_xor_sync(0xffffffffu, s, o);
        float inv = 1.f / s;
        float a0 = e0 * inv, a1 = e1 * inv;
        adup[l * 16 + w * 2]            = a0;
        adup[l * 16 + w * 2 + 1]        = a0;
        adup[(l + 32) * 16 + w * 2]     = a1;
        adup[(l + 32) * 16 + w * 2 + 1] = a1;
    }
    __syncthreads();

    // ---- phase 2: thread (c4 = t&63, q = t>>6) rows {q+4j}, all 8 heads ----
    {
        const int c4 = t & 63, q = t >> 6;
        unsigned long long acc[NH][2];
        #pragma unroll
        for (int h = 0; h < NH; h++) { acc[h][0] = 0ull; acc[h][1] = 0ull; }
        #pragma unroll
        for (int j = 0; j < 16; j++) {
            int n = q + 4 * j;
            ulonglong2 x = *reinterpret_cast<const ulonglong2*>(nbt + c4 * 65 + n);
            const ulonglong2* ap = reinterpret_cast<const ulonglong2*>(adup + n * 16);
            ulonglong2 a01 = ap[0], a23 = ap[1], a45 = ap[2], a67 = ap[3];
            fma2(acc[0][0], a01.x, x.x); fma2(acc[0][1], a01.x, x.y);
            fma2(acc[1][0], a01.y, x.x); fma2(acc[1][1], a01.y, x.y);
            fma2(acc[2][0], a23.x, x.x); fma2(acc[2][1], a23.x, x.y);
            fma2(acc[3][0], a23.y, x.x); fma2(acc[3][1], a23.y, x.y);
            fma2(acc[4][0], a45.x, x.x); fma2(acc[4][1], a45.x, x.y);
            fma2(acc[5][0], a45.y, x.x); fma2(acc[5][1], a45.y, x.y);
            fma2(acc[6][0], a67.x, x.x); fma2(acc[6][1], a67.x, x.y);
            fma2(acc[7][0], a67.y, x.x); fma2(acc[7][1], a67.y, x.y);
        }
        __syncthreads();         // nbt dead; part2 aliases it
        ulonglong2* p2 = (ulonglong2*)sm;
        #pragma unroll
        for (int h = 0; h < NH; h++) {
            ulonglong2 v; v.x = acc[h][0]; v.y = acc[h][1];
            p2[h * 256 + q * 64 + c4] = v;
        }
    }
    __syncthreads();

    // ---- reduce partials over q, write ctx ----
    {
        const float4* p4 = (const float4*)sm;
        float4* cg = (float4*)(d_ctx + (long)b * 2048);
        #pragma unroll
        for (int k = 0; k < 2; k++) {
            int o = t + k * 256;
            int h = o >> 6, c4o = o & 63;
            float4 r0 = p4[h * 256 + 0 * 64 + c4o];
            float4 r1 = p4[h * 256 + 1 * 64 + c4o];
            float4 r2 = p4[h * 256 + 2 * 64 + c4o];
            float4 r3 = p4[h * 256 + 3 * 64 + c4o];
            float4 r;
            r.x = (r0.x + r1.x) + (r2.x + r3.x);
            r.y = (r0.y + r1.y) + (r2.y + r3.y);
            r.z = (r0.z + r1.z) + (r2.z + r3.z);
            r.w = (r0.w + r1.w) + (r2.w + r3.w);
            cg[o] = r;
        }
    }
}

// ---------------- LayerNorm + ReLU (warp per row, float4) ----------------
__global__ void ln_relu_kernel(const float* __restrict__ g,
                               const float* __restrict__ be,
                               float* __restrict__ out) {
    const int b = blockIdx.x * 8 + (threadIdx.x >> 5);
    const int l = threadIdx.x & 31;
    const float4* yr = (const float4*)(d_y + (long)b * DM) + l * 2;
    float4 v0 = yr[0], v1 = yr[1];
    float s = v0.x + v0.y + v0.z + v0.w + v1.x + v1.y + v1.z + v1.w;
    #pragma unroll
    for (int o = 16; o; o >>= 1) s += __shfl_xor_sync(0xffffffffu, s, o);
    float mu = s * (1.f / 256.f);
    float vs = 0.f;
    {
        float d;
        d = v0.x - mu; vs += d * d;  d = v0.y - mu; vs += d * d;
        d = v0.z - mu; vs += d * d;  d = v0.w - mu; vs += d * d;
        d = v1.x - mu; vs += d * d;  d = v1.y - mu; vs += d * d;
        d = v1.z - mu; vs += d * d;  d = v1.w - mu; vs += d * d;
    }
    #pragma unroll
    for (int o = 16; o; o >>= 1) vs += __shfl_xor_sync(0xffffffffu, vs, o);
    float r = rsqrtf(vs * (1.f / 256.f) + 1e-5f);
    const float4* gp = (const float4*)g + l * 2;
    const float4* bp = (const float4*)be + l * 2;
    float4* op = (float4*)(out + (long)b * DM) + l * 2;
    float4 g0 = gp[0], g1 = gp[1], b0 = bp[0], b1 = bp[1];
    float4 o0, o1;
    o0.x = fmaxf((v0.x - mu) * r * g0.x + b0.x, 0.f);
    o0.y = fmaxf((v0.y - mu) * r * g0.y + b0.y, 0.f);
    o0.z = fmaxf((v0.z - mu) * r * g0.z + b0.z, 0.f);
    o0.w = fmaxf((v0.w - mu) * r * g0.w + b0.w, 0.f);
    o1.x = fmaxf((v1.x - mu) * r * g1.x + b1.x, 0.f);
    o1.y = fmaxf((v1.y - mu) * r * g1.y + b1.y, 0.f);
    o1.z = fmaxf((v1.z - mu) * r * g1.z + b1.z, 0.f);
    o1.w = fmaxf((v1.w - mu) * r * g1.w + b1.w, 0.f);
    op[0] = o0; op[1] = o1;
}

// ---------------- host launcher ----------------
extern "C" void kernel_launch(void* const* d_in, const int* in_sizes, int n_in,
                              void* d_out, int out_size) {
    const float* cde = (const float*)d_in[0];
    const float* nb  = (const float*)d_in[1];
    const unsigned int* et = (const unsigned int*)d_in[2];
    const float* Wq = (const float*)d_in[3];
    const float* bq = (const float*)d_in[4];
    const float* Wk = (const float*)d_in[5];
    const float* bk = (const float*)d_in[6];
    const float* Wv = (const float*)d_in[7];
    const float* bv = (const float*)d_in[8];
    const float* Wo = (const float*)d_in[9];
    const float* bo = (const float*)d_in[10];
    const float* ebt = (const float*)d_in[11];
    const float* Wf = (const float*)d_in[12];
    const float* bfv = (const float*)d_in[13];
    const float* lg = (const float*)d_in[14];
    const float* lb = (const float*)d_in[15];
    float* out = (float*)d_out;

    float *pQ, *pU, *pCtx, *pAtt, *pY, *pWkT, *pWoT, *pWc, *pB1;
    cudaGetSymbolAddress((void**)&pQ,   d_Q);
    cudaGetSymbolAddress((void**)&pU,   d_U);
    cudaGetSymbolAddress((void**)&pCtx, d_ctx);
    cudaGetSymbolAddress((void**)&pAtt, d_att);
    cudaGetSymbolAddress((void**)&pY,   d_y);
    cudaGetSymbolAddress((void**)&pWkT, d_WkT);
    cudaGetSymbolAddress((void**)&pWoT, d_WoT);
    cudaGetSymbolAddress((void**)&pWc,  d_Wc);
    cudaGetSymbolAddress((void**)&pB1,  d_b1);

    cudaFuncSetAttribute(attn_kernel,
                         cudaFuncAttributeMaxDynamicSharedMemorySize,
                         ATTN_SMEM_BYTES);

    // 1) prep (transposes + b1 + edge detect)
    prep_kernel<<<256, 256>>>(Wk, Wo, Wf, bo, bfv, et);
    // 2) Q = cde @ Wq^T + bq
    gemm2_kernel<64, 64, 8, 4><<<dim3(DM / 64, BATCH / 64, 1), 128>>>(
        cde, DM, 0, Wq, DM, 0, nullptr, 0, nullptr, 0,
        bq, 0, pQ, DM, 0, DM, DM, 1.f);
    // 3) U[b,h,:] = SCALE * Qh^T Wk_h
    gemm2_kernel<64, 64, 8, 4><<<dim3(DM / 64, BATCH / 64, NH), 128>>>(
        pQ, DM, HD, pWkT, HD, (long)DM * HD, nullptr, 0, nullptr, 0,
        nullptr, 0, pU, NH * DM, DM, HD, HD, SCALE);
    // 4) fused attention  (launch #4 -> ncu capture target)
    attn_kernel<<<BATCH, 256, ATTN_SMEM_BYTES>>>(nb, et, ebt, bk);
    // 5) Wc = Wf[:, :256] @ Wo
    gemm2_kernel<64, 64, 8, 4><<<dim3(DM / 64, DM / 64, 1), 128>>>(
        Wf, 2 * DM, 0, pWoT, DM, 0, nullptr, 0, nullptr, 0,
        nullptr, 0, pWc, DM, 0, DM, DM, 1.f);
    // 6) att[b, h*32+d] = Wv_h[d,:].ctx[b,h,:] + bv
    gemm2_kernel<128, 32, 8, 2><<<dim3(1, BATCH / 128, NH), 256>>>(
        pCtx, NH * DM, DM, Wv, DM, (long)HD * DM, nullptr, 0, nullptr, 0,
        bv, HD, pAtt, DM, HD, DM, DM, 1.f);
    // 7) y = att @ Wc^T + cde @ Wf[:,256:]^T + b1
    gemm2_kernel<64, 64, 8, 4><<<dim3(DM / 64, BATCH / 64, 1), 128>>>(
        pAtt, DM, 0, pWc, DM, 0, cde, DM, Wf + DM, 2 * DM,
        pB1, 0, pY, DM, 0, DM, 2 * DM, 1.f);
    // 8) LayerNorm + ReLU -> out
    ln_relu_kernel<<<BATCH / 8, 256>>>(lg, lb, out);
}

// round 14
// speedup vs baseline: 1.1042x; 1.1042x over previous
#include <cuda_runtime.h>
#include <cuda_bf16.h>
#include <math.h>

#define BATCH 4096
#define NNB   64
#define DM    256
#define NH    8
#define HD    32
#define SCALE 0.17677669529663687f   // 1/sqrt(32)

// ---------------- f32x2 packed helpers ----------------
__device__ __forceinline__ void fma2(unsigned long long& d,
                                     unsigned long long a,
                                     unsigned long long b) {
    asm("fma.rn.f32x2 %0, %1, %2, %0;" : "+l"(d) : "l"(a), "l"(b));
}
__device__ __forceinline__ float2 upk(unsigned long long v) {
    float2 r;
    asm("mov.b64 {%0, %1}, %2;" : "=f"(r.x), "=f"(r.y) : "l"(v));
    return r;
}
__device__ __forceinline__ unsigned int s2u(const void* p) {
    unsigned int a;
    asm("{ .reg .u64 t; cvta.to.shared.u64 t, %1; cvt.u32.u64 %0, t; }"
        : "=r"(a) : "l"(p));
    return a;
}
__device__ __forceinline__ void cp16(unsigned int saddr, const void* g) {
    asm volatile("cp.async.ca.shared.global [%0], [%1], 16;"
                 :: "r"(saddr), "l"(g) : "memory");
}

// ---------------- scratch ----------------
__device__ float d_Q  [BATCH * DM];
__device__ float d_U  [BATCH * NH * DM];
__device__ float d_ctx[BATCH * NH * DM];
__device__ float d_att[BATCH * DM];
__device__ float d_y  [BATCH * DM];
__device__ float d_WkT[NH * DM * HD];      // [h][c][d]
__device__ float d_WoT[DM * DM];
__device__ float d_Wc [DM * DM];
__device__ float d_b1 [DM];
__device__ unsigned int d_or = 0u;         // OR of odd words; 0 => int64

// ---------------- prep: transposes + b1 + edge-dtype detect ----------------
__global__ void prep_kernel(const float* __restrict__ Wk,
                            const float* __restrict__ Wo,
                            const float* __restrict__ Wf,
                            const float* __restrict__ bo,
                            const float* __restrict__ bfv,
                            const unsigned int* __restrict__ e32) {
    const int blk = blockIdx.x, t = threadIdx.x;
    const int i = blk * 256 + t;                 // 0..65535
    { int dd = i & 31, c = (i >> 5) & 255, h = i >> 13;
      d_WkT[i] = Wk[(h * HD + dd) * DM + c]; }
    { int j = i >> 8, m = i & 255;
      d_WoT[i] = Wo[m * DM + j]; }
    if (blk < 32) {
        int o = blk * 8 + (t >> 5), l = t & 31;
        float s = 0.f;
        #pragma unroll
        for (int m = l; m < DM; m += 32) s += Wf[o * 2 * DM + m] * bo[m];
        #pragma unroll
        for (int off = 16; off; off >>= 1) s += __shfl_xor_sync(0xffffffffu, s, off);
        if (l == 0) d_b1[o] = bfv[o] + s;
    }
    unsigned int acc = 0u;
    #pragma unroll
    for (int w = i; w < BATCH * NNB; w += 65536) acc |= e32[2 * w + 1];
    #pragma unroll
    for (int o = 16; o; o >>= 1) acc |= __shfl_xor_sync(0xffffffffu, acc, o);
    __shared__ unsigned int sOr;
    if (t == 0) sOr = 0u;
    __syncthreads();
    if ((t & 31) == 0 && acc) atomicOr(&sOr, acc);
    __syncthreads();
    if (t == 0 && sOr) atomicOr(&d_or, sOr);
}

// ---------------- double-buffered NT GEMM (float4 smem reads) ---------------
template<int BM, int BN, int TM, int TN>
__global__ void gemm2_kernel(const float* __restrict__ A1, int lda1, long az1,
                             const float* __restrict__ B1, int ldb1, long bz1,
                             const float* __restrict__ A2, int lda2,
                             const float* __restrict__ B2, int ldb2,
                             const float* __restrict__ bias, long biasz,
                             float* __restrict__ C, int ldc, long cz,
                             int K1, int Ktot, float alpha) {
    constexpr int BK = 16;
    constexpr int NT = (BM / TM) * (BN / TN);
    constexpr int PAD = 4;
    constexpr int A4 = BM * BK / 4;
    constexpr int B4 = BN * BK / 4;
    constexpr int NA = (A4 + NT - 1) / NT;
    constexpr int NB = (B4 + NT - 1) / NT;

    __shared__ __align__(16) float As[2][BK][BM + PAD];
    __shared__ __align__(16) float Bs[2][BK][BN + PAD];

    const int tid = threadIdx.x;
    const int tx = tid % (BN / TN);
    const int ty = tid / (BN / TN);
    const int row0 = blockIdx.y * BM;
    const int col0 = blockIdx.x * BN;
    const int z = blockIdx.z;

    const float* A1g = A1 + (long)z * az1;
    const float* B1g = B1 + (long)z * bz1;
    float* Cg = C + (long)z * cz;
    const float* biasg = bias ? bias + (long)z * biasz : nullptr;

    float4 ra[NA], rb[NB];

    auto fetch = [&](int t) {
        int k0 = t * BK;
        const float *Ap, *Bp; int lda, ldb, k;
        if (k0 < K1) { Ap = A1g; lda = lda1; Bp = B1g; ldb = ldb1; k = k0; }
        else         { Ap = A2;  lda = lda2; Bp = B2;  ldb = ldb2; k = k0 - K1; }
        #pragma unroll
        for (int i = 0; i < NA; i++) {
            int f = tid + i * NT;
            if (f < A4) {
                int r = f >> 2, kq = f & 3;
                ra[i] = *reinterpret_cast<const float4*>(Ap + (long)(row0 + r) * lda + k + kq * 4);
            }
        }
        #pragma unroll
        for (int i = 0; i < NB; i++) {
            int f = tid + i * NT;
            if (f < B4) {
                int n = f >> 2, kq = f & 3;
                rb[i] = *reinterpret_cast<const float4*>(Bp + (long)(col0 + n) * ldb + k + kq * 4);
            }
        }
    };
    auto stage = [&](int buf) {
        #pragma unroll
        for (int i = 0; i < NA; i++) {
            int f = tid + i * NT;
            if (f < A4) {
                int r = f >> 2, kq = f & 3;
                As[buf][kq * 4 + 0][r] = ra[i].x;
                As[buf][kq * 4 + 1][r] = ra[i].y;
                As[buf][kq * 4 + 2][r] = ra[i].z;
                As[buf][kq * 4 + 3][r] = ra[i].w;
            }
        }
        #pragma unroll
        for (int i = 0; i < NB; i++) {
            int f = tid + i * NT;
            if (f < B4) {
                int n = f >> 2, kq = f & 3;
                Bs[buf][kq * 4 + 0][n] = rb[i].x;
                Bs[buf][kq * 4 + 1][n] = rb[i].y;
                Bs[buf][kq * 4 + 2][n] = rb[i].z;
                Bs[buf][kq * 4 + 3][n] = rb[i].w;
            }
        }
    };

    float acc[TM][TN];
    #pragma unroll
    for (int i = 0; i < TM; i++)
        #pragma unroll
        for (int j = 0; j < TN; j++) acc[i][j] = 0.f;

    fetch(0); stage(0); __syncthreads();
    const int ntiles = Ktot / BK;
    for (int t = 0; t < ntiles; t++) {
        int cur = t & 1;
        if (t + 1 < ntiles) fetch(t + 1);
        #pragma unroll
        for (int kk = 0; kk < BK; kk++) {
            float a[TM], b[TN];
            if constexpr (TM % 4 == 0) {
                const float4* a4 = reinterpret_cast<const float4*>(&As[cur][kk][ty * TM]);
                #pragma unroll
                for (int i = 0; i < TM / 4; i++) {
                    float4 v = a4[i];
                    a[4 * i + 0] = v.x; a[4 * i + 1] = v.y;
                    a[4 * i + 2] = v.z; a[4 * i + 3] = v.w;
                }
            } else {
                #pragma unroll
                for (int i = 0; i < TM; i++) a[i] = As[cur][kk][ty * TM + i];
            }
            if constexpr (TN % 4 == 0) {
                const float4* b4 = reinterpret_cast<const float4*>(&Bs[cur][kk][tx * TN]);
                #pragma unroll
                for (int j = 0; j < TN / 4; j++) {
                    float4 v = b4[j];
                    b[4 * j + 0] = v.x; b[4 * j + 1] = v.y;
                    b[4 * j + 2] = v.z; b[4 * j + 3] = v.w;
                }
            } else if constexpr (TN % 2 == 0) {
                const float2* b2 = reinterpret_cast<const float2*>(&Bs[cur][kk][tx * TN]);
                #pragma unroll
                for (int j = 0; j < TN / 2; j++) {
                    float2 v = b2[j];
                    b[2 * j + 0] = v.x; b[2 * j + 1] = v.y;
                }
            } else {
                #pragma unroll
                for (int j = 0; j < TN; j++) b[j] = Bs[cur][kk][tx * TN + j];
            }
            #pragma unroll
            for (int i = 0; i < TM; i++)
                #pragma unroll
                for (int j = 0; j < TN; j++) acc[i][j] += a[i] * b[j];
        }
        if (t + 1 < ntiles) stage(cur ^ 1);
        __syncthreads();
    }

    #pragma unroll
    for (int i = 0; i < TM; i++) {
        int r = row0 + ty * TM + i;
        #pragma unroll
        for (int j = 0; j < TN; j++) {
            int c = col0 + tx * TN + j;
            float v = alpha * acc[i][j];
            if (biasg) v += biasg[c];
            Cg[(long)r * ldc + c] = v;
        }
    }
}

// ---------------- fused attention v7 (R11 exact — proven 100.3 us) ----------
#define U_S_OFF   16640
#define PART_OFF  18688
#define ADUP_OFF  22784
#define TBL_OFF   23808
#define KB_OFF    23872
#define ET_OFF    23880
#define ATTN_SMEM_BYTES (23944 * 4)

__global__ __launch_bounds__(256) void attn_kernel(
        const float* __restrict__ nb,
        const unsigned int* __restrict__ e32,
        const float* __restrict__ ebt,
        const float* __restrict__ bk) {
    extern __shared__ __align__(16) float sm[];
    float4* nbt  = (float4*)sm;
    float*  u_s  = sm + U_S_OFF;
    float*  part = sm + PART_OFF;
    float*  adup = sm + ADUP_OFF;
    float*  tbl  = sm + TBL_OFF;
    float*  kb_s = sm + KB_OFF;
    int*    et_s = (int*)(sm + ET_OFF);

    const int b = blockIdx.x;
    const int t = threadIdx.x;

    // ---- stage nb (transposed) + u via cp.async; overlap with small loads ----
    const float4* nbg = (const float4*)(nb + (long)b * NNB * DM);
    #pragma unroll
    for (int i = 0; i < 16; i++) {
        int f = t + i * 256;
        int row = f >> 6, c4 = f & 63;
        cp16(s2u(&nbt[c4 * 65 + row]), &nbg[f]);
    }
    const float4* ug = (const float4*)(d_U + (long)b * 2048);
    cp16(s2u(u_s + t * 4),        &ug[t]);
    cp16(s2u(u_s + 1024 + t * 4), &ug[256 + t]);
    asm volatile("cp.async.commit_group;" ::: "memory");

    if (t < NNB) {
        int v = (d_or == 0u) ? (int)e32[(long)b * (2 * NNB) + 2 * t]
                             : (int)e32[(long)b * NNB + t];
        et_s[t] = v;
        tbl[t] = ebt[t];
    }
    {
        const int w = t >> 5, l = t & 31;
        float s = d_Q[(long)b * DM + w * HD + l] * bk[w * HD + l];
        #pragma unroll
        for (int o = 16; o; o >>= 1) s += __shfl_xor_sync(0xffffffffu, s, o);
        if (l == 0) kb_s[w] = SCALE * s;
    }
    asm volatile("cp.async.wait_group 0;" ::: "memory");
    __syncthreads();

    // ---- phase 1: thread (n2 = t&31 -> {n2, n2+32}, q8 = t>>5), FFMA2 ----
    {
        const int n2 = t & 31, q8 = t >> 5;
        unsigned long long accA[NH], accB[NH];
        #pragma unroll
        for (int h = 0; h < NH; h++) { accA[h] = 0ull; accB[h] = 0ull; }
        #pragma unroll
        for (int c4 = 0; c4 < 8; c4++) {
            int slot = q8 * 8 + c4;
            ulonglong2 xA = *reinterpret_cast<const ulonglong2*>(nbt + slot * 65 + n2);
            ulonglong2 xB = *reinterpret_cast<const ulonglong2*>(nbt + slot * 65 + n2 + 32);
            #pragma unroll
            for (int h = 0; h < NH; h++) {
                ulonglong2 u = *reinterpret_cast<const ulonglong2*>(
                    u_s + h * DM + q8 * 32 + c4 * 4);
                fma2(accA[h], u.x, xA.x);
                fma2(accA[h], u.y, xA.y);
                fma2(accB[h], u.x, xB.x);
                fma2(accB[h], u.y, xB.y);
            }
        }
        #pragma unroll
        for (int h = 0; h < NH; h++) {
            float2 vA = upk(accA[h]);
            float2 vB = upk(accB[h]);
            part[h * 512 + q8 * 64 + n2]      = vA.x + vA.y;
            part[h * 512 + q8 * 64 + n2 + 32] = vB.x + vB.y;
        }
    }
    __syncthreads();

    // ---- softmax with inline combine: warp w = head w; writes adup pairs ----
    {
        const int w = t >> 5, l = t & 31;
        float lg0 = kb_s[w] + tbl[et_s[l] * NH + w];
        float lg1 = kb_s[w] + tbl[et_s[l + 32] * NH + w];
        #pragma unroll
        for (int q = 0; q < 8; q++) {
            lg0 += part[w * 512 + q * 64 + l];
            lg1 += part[w * 512 + q * 64 + l + 32];
        }
        float m = fmaxf(lg0, lg1);
        #pragma unroll
        for (int o = 16; o; o >>= 1) m = fmaxf(m, __shfl_xor_sync(0xffffffffu, m, o));
        float e0 = __expf(lg0 - m), e1 = __expf(lg1 - m);
        float s = e0 + e1;
        #pragma unroll
        for (int o = 16; o; o >>= 1) s += __shfl_xor_sync(0xffffffffu, s, o);
        float inv = 1.f / s;
        float a0 = e0 * inv, a1 = e1 * inv;
        adup[l * 16 + w * 2]            = a0;
        adup[l * 16 + w * 2 + 1]        = a0;
        adup[(l + 32) * 16 + w * 2]     = a1;
        adup[(l + 32) * 16 + w * 2 + 1] = a1;
    }
    __syncthreads();

    // ---- phase 2: thread (c4 = t&63, q = t>>6) rows {q+4j}, all 8 heads ----
    {
        const int c4 = t & 63, q = t >> 6;
        unsigned long long acc[NH][2];
        #pragma unroll
        for (int h = 0; h < NH; h++) { acc[h][0] = 0ull; acc[h][1] = 0ull; }
        #pragma unroll
        for (int j = 0; j < 16; j++) {
            int n = q + 4 * j;
            ulonglong2 x = *reinterpret_cast<const ulonglong2*>(nbt + c4 * 65 + n);
            const ulonglong2* ap = reinterpret_cast<const ulonglong2*>(adup + n * 16);
            ulonglong2 a01 = ap[0], a23 = ap[1], a45 = ap[2], a67 = ap[3];
            fma2(acc[0][0], a01.x, x.x); fma2(acc[0][1], a01.x, x.y);
            fma2(acc[1][0], a01.y, x.x); fma2(acc[1][1], a01.y, x.y);
            fma2(acc[2][0], a23.x, x.x); fma2(acc[2][1], a23.x, x.y);
            fma2(acc[3][0], a23.y, x.x); fma2(acc[3][1], a23.y, x.y);
            fma2(acc[4][0], a45.x, x.x); fma2(acc[4][1], a45.x, x.y);
            fma2(acc[5][0], a45.y, x.x); fma2(acc[5][1], a45.y, x.y);
            fma2(acc[6][0], a67.x, x.x); fma2(acc[6][1], a67.x, x.y);
            fma2(acc[7][0], a67.y, x.x); fma2(acc[7][1], a67.y, x.y);
        }
        __syncthreads();                 // nbt dead; part2 aliases it
        ulonglong2* p2 = (ulonglong2*)sm;
        #pragma unroll
        for (int h = 0; h < NH; h++) {
            ulonglong2 v; v.x = acc[h][0]; v.y = acc[h][1];
            p2[h * 256 + q * 64 + c4] = v;
        }
    }
    __syncthreads();

    // ---- reduce partials over q, write ctx ----
    {
        const float4* p4 = (const float4*)sm;
        float4* cg = (float4*)(d_ctx + (long)b * 2048);
        #pragma unroll
        for (int k = 0; k < 2; k++) {
            int o = t + k * 256;
            int h = o >> 6, c4o = o & 63;
            float4 r0 = p4[h * 256 + 0 * 64 + c4o];
            float4 r1 = p4[h * 256 + 1 * 64 + c4o];
            float4 r2 = p4[h * 256 + 2 * 64 + c4o];
            float4 r3 = p4[h * 256 + 3 * 64 + c4o];
            float4 r;
            r.x = (r0.x + r1.x) + (r2.x + r3.x);
            r.y = (r0.y + r1.y) + (r2.y + r3.y);
            r.z = (r0.z + r1.z) + (r2.z + r3.z);
            r.w = (r0.w + r1.w) + (r2.w + r3.w);
            cg[o] = r;
        }
    }
}

// ---------------- LayerNorm + ReLU (warp per row, float4) ----------------
__global__ void ln_relu_kernel(const float* __restrict__ g,
                               const float* __restrict__ be,
                               float* __restrict__ out) {
    const int b = blockIdx.x * 8 + (threadIdx.x >> 5);
    const int l = threadIdx.x & 31;
    const float4* yr = (const float4*)(d_y + (long)b * DM) + l * 2;
    float4 v0 = yr[0], v1 = yr[1];
    float s = v0.x + v0.y + v0.z + v0.w + v1.x + v1.y + v1.z + v1.w;
    #pragma unroll
    for (int o = 16; o; o >>= 1) s += __shfl_xor_sync(0xffffffffu, s, o);
    float mu = s * (1.f / 256.f);
    float vs = 0.f;
    {
        float d;
        d = v0.x - mu; vs += d * d;  d = v0.y - mu; vs += d * d;
        d = v0.z - mu; vs += d * d;  d = v0.w - mu; vs += d * d;
        d = v1.x - mu; vs += d * d;  d = v1.y - mu; vs += d * d;
        d = v1.z - mu; vs += d * d;  d = v1.w - mu; vs += d * d;
    }
    #pragma unroll
    for (int o = 16; o; o >>= 1) vs += __shfl_xor_sync(0xffffffffu, vs, o);
    float r = rsqrtf(vs * (1.f / 256.f) + 1e-5f);
    const float4* gp = (const float4*)g + l * 2;
    const float4* bp = (const float4*)be + l * 2;
    float4* op = (float4*)(out + (long)b * DM) + l * 2;
    float4 g0 = gp[0], g1 = gp[1], b0 = bp[0], b1 = bp[1];
    float4 o0, o1;
    o0.x = fmaxf((v0.x - mu) * r * g0.x + b0.x, 0.f);
    o0.y = fmaxf((v0.y - mu) * r * g0.y + b0.y, 0.f);
    o0.z = fmaxf((v0.z - mu) * r * g0.z + b0.z, 0.f);
    o0.w = fmaxf((v0.w - mu) * r * g0.w + b0.w, 0.f);
    o1.x = fmaxf((v1.x - mu) * r * g1.x + b1.x, 0.f);
    o1.y = fmaxf((v1.y - mu) * r * g1.y + b1.y, 0.f);
    o1.z = fmaxf((v1.z - mu) * r * g1.z + b1.z, 0.f);
    o1.w = fmaxf((v1.w - mu) * r * g1.w + b1.w, 0.f);
    op[0] = o0; op[1] = o1;
}

// ---------------- host launcher ----------------
extern "C" void kernel_launch(void* const* d_in, const int* in_sizes, int n_in,
                              void* d_out, int out_size) {
    const float* cde = (const float*)d_in[0];
    const float* nb  = (const float*)d_in[1];
    const unsigned int* et = (const unsigned int*)d_in[2];
    const float* Wq = (const float*)d_in[3];
    const float* bq = (const float*)d_in[4];
    const float* Wk = (const float*)d_in[5];
    const float* bk = (const float*)d_in[6];
    const float* Wv = (const float*)d_in[7];
    const float* bv = (const float*)d_in[8];
    const float* Wo = (const float*)d_in[9];
    const float* bo = (const float*)d_in[10];
    const float* ebt = (const float*)d_in[11];
    const float* Wf = (const float*)d_in[12];
    const float* bfv = (const float*)d_in[13];
    const float* lg = (const float*)d_in[14];
    const float* lb = (const float*)d_in[15];
    float* out = (float*)d_out;

    float *pQ, *pU, *pCtx, *pAtt, *pY, *pWkT, *pWoT, *pWc, *pB1;
    cudaGetSymbolAddress((void**)&pQ,   d_Q);
    cudaGetSymbolAddress((void**)&pU,   d_U);
    cudaGetSymbolAddress((void**)&pCtx, d_ctx);
    cudaGetSymbolAddress((void**)&pAtt, d_att);
    cudaGetSymbolAddress((void**)&pY,   d_y);
    cudaGetSymbolAddress((void**)&pWkT, d_WkT);
    cudaGetSymbolAddress((void**)&pWoT, d_WoT);
    cudaGetSymbolAddress((void**)&pWc,  d_Wc);
    cudaGetSymbolAddress((void**)&pB1,  d_b1);

    cudaFuncSetAttribute(attn_kernel,
                         cudaFuncAttributeMaxDynamicSharedMemorySize,
                         ATTN_SMEM_BYTES);

    // 1) prep (transposes + b1 + edge detect)
    prep_kernel<<<256, 256>>>(Wk, Wo, Wf, bo, bfv, et);
    // 2) Q = cde @ Wq^T + bq
    gemm2_kernel<64, 64, 8, 4><<<dim3(DM / 64, BATCH / 64, 1), 128>>>(
        cde, DM, 0, Wq, DM, 0, nullptr, 0, nullptr, 0,
        bq, 0, pQ, DM, 0, DM, DM, 1.f);
    // 3) U[b,h,:] = SCALE * Qh^T Wk_h
    gemm2_kernel<64, 64, 8, 4><<<dim3(DM / 64, BATCH / 64, NH), 128>>>(
        pQ, DM, HD, pWkT, HD, (long)DM * HD, nullptr, 0, nullptr, 0,
        nullptr, 0, pU, NH * DM, DM, HD, HD, SCALE);
    // 4) fused attention  (launch #4 -> ncu capture target)
    attn_kernel<<<BATCH, 256, ATTN_SMEM_BYTES>>>(nb, et, ebt, bk);
    // 5) Wc = Wf[:, :256] @ Wo
    gemm2_kernel<64, 64, 8, 4><<<dim3(DM / 64, DM / 64, 1), 128>>>(
        Wf, 2 * DM, 0, pWoT, DM, 0, nullptr, 0, nullptr, 0,
        nullptr, 0, pWc, DM, 0, DM, DM, 1.f);
    // 6) att[b, h*32+d] = Wv_h[d,:].ctx[b,h,:] + bv
    gemm2_kernel<128, 32, 8, 2><<<dim3(1, BATCH / 128, NH), 256>>>(
        pCtx, NH * DM, DM, Wv, DM, (long)HD * DM, nullptr, 0, nullptr, 0,
        bv, HD, pAtt, DM, HD, DM, DM, 1.f);
    // 7) y = att @ Wc^T + cde @ Wf[:,256:]^T + b1
    gemm2_kernel<64, 64, 8, 4><<<dim3(DM / 64, BATCH / 64, 1), 128>>>(
        pAtt, DM, 0, pWc, DM, 0, cde, DM, Wf + DM, 2 * DM,
        pB1, 0, pY, DM, 0, DM, 2 * DM, 1.f);
    // 8) LayerNorm + ReLU -> out
    ln_relu_kernel<<<BATCH / 8, 256>>>(lg, lb, out);
}